// round 6
// baseline (speedup 1.0000x reference)
#include <cuda_runtime.h>

#define BB 16
#define CC 128
#define NN 1024
#define KK 9

// ---- scratch (device globals; no allocation allowed) ----
__device__ float  g_sq[BB*NN];
__device__ float  g_u[BB*NN*CC];     // u = f@W1[:C] + b1
__device__ float  g_v[BB*NN*CC];     // v = f@W1[C:]
__device__ int    g_idx[BB*NN*KK];   // GLOBAL point indices (b*NN + m)
__device__ float  g_pre[BB*NN*CC];   // pre-BN output, (b,n,c)
__device__ double g_dsum[CC];
__device__ double g_dsqs[CC];
__device__ float  g_scale[CC];
__device__ float  g_shift[CC];

// ---------------- K0: zero BN accumulators ----------------
__global__ void k_init() {
    int t = threadIdx.x;
    g_dsum[t] = 0.0;
    g_dsqs[t] = 0.0;
}

// ---------------- K1: per-point sq, u, v ----------------
// block = 128 threads, handles 16 consecutive points (same b since 1024%16==0)
__global__ void __launch_bounds__(128) k_point(
    const float* __restrict__ x, const float* __restrict__ W1,
    const float* __restrict__ b1)
{
    __shared__ float fs[16*130];   // stride 130: conflict-free stores
    int t = threadIdx.x;
    int base = blockIdx.x * 16;
    int b = base / NN, n0 = base % NN;

    // load 16 points x 128 channels (coalesced over n)
    {
        int p = t & 15, c0 = t >> 4;   // c0 in 0..7
        #pragma unroll
        for (int i = 0; i < 16; i++) {
            int c = c0 + i*8;
            fs[p*130 + c] = x[(b*CC + c)*NN + n0 + p];
        }
    }
    __syncthreads();

    if (t < 16) {
        float s = 0.f;
        #pragma unroll 4
        for (int c = 0; c < CC; c++) { float f = fs[t*130+c]; s += f*f; }
        g_sq[base + t] = s;
    }

    int j = t;
    float accU[16], accV[16];
    #pragma unroll
    for (int p = 0; p < 16; p++) { accU[p]=0.f; accV[p]=0.f; }
    for (int c = 0; c < CC; c++) {
        float wa = W1[c*CC + j];
        float wb = W1[(CC+c)*CC + j];
        #pragma unroll
        for (int p = 0; p < 16; p++) {
            float f = fs[p*130 + c];
            accU[p] = fmaf(f, wa, accU[p]);
            accV[p] = fmaf(f, wb, accV[p]);
        }
    }
    float bj = b1[j];
    #pragma unroll
    for (int p = 0; p < 16; p++) {
        g_u[(base+p)*CC + j] = accU[p] + bj;
        g_v[(base+p)*CC + j] = accV[p];
    }
}

// ---------------- K2: exact KNN (top-9 smallest d2) ----------------
// block = (n-tile of 128, b); thread owns one query row in registers.
// m-tiles of 64 staged in smem as [c][m] so vec4 reads over m broadcast.
__global__ void __launch_bounds__(128) k_knn(const float* __restrict__ x)
{
    __shared__ float Am[CC*64];   // [c][m]
    __shared__ float sqs[64];
    int t = threadIdx.x;
    int b = blockIdx.y;
    int n = blockIdx.x * 128 + t;

    float rf[CC];
    #pragma unroll
    for (int c = 0; c < CC; c++) rf[c] = x[(b*CC + c)*NN + n];
    float sq_n = g_sq[b*NN + n];

    float bd[KK]; int bi[KK];
    #pragma unroll
    for (int k = 0; k < KK; k++) { bd[k] = 3.4e38f; bi[k] = 0; }
    float wmax = 3.4e38f; int wpos = 0;

    for (int mt = 0; mt < NN/64; mt++) {
        int mb = mt*64;
        __syncthreads();
        for (int i = t; i < CC*64; i += 128) {
            int c = i >> 6, m = i & 63;
            Am[c*64 + m] = x[(b*CC + c)*NN + mb + m];   // coalesced ld, conflict-free st
        }
        if (t < 64) sqs[t] = g_sq[b*NN + mb + t];
        __syncthreads();

        for (int mg = 0; mg < 64; mg += 4) {
            float d0=0.f, d1=0.f, d2a=0.f, d3=0.f;
            #pragma unroll
            for (int c = 0; c < CC; c++) {
                float4 am = *(const float4*)&Am[c*64 + mg];   // broadcast
                d0 = fmaf(rf[c], am.x, d0);
                d1 = fmaf(rf[c], am.y, d1);
                d2a= fmaf(rf[c], am.z, d2a);
                d3 = fmaf(rf[c], am.w, d3);
            }
            float dots[4] = {d0, d1, d2a, d3};
            #pragma unroll
            for (int q = 0; q < 4; q++) {
                int m = mb + mg + q;
                float d2v = sq_n + sqs[mg+q] - 2.f*dots[q];
                if (d2v < wmax) {
                    #pragma unroll
                    for (int k = 0; k < KK; k++)
                        if (k == wpos) { bd[k] = d2v; bi[k] = m; }
                    wmax = bd[0]; wpos = 0;
                    #pragma unroll
                    for (int k = 1; k < KK; k++)
                        if (bd[k] > wmax) { wmax = bd[k]; wpos = k; }
                }
            }
        }
    }
    // store GLOBAL point index so downstream gathers stay in batch b
    #pragma unroll
    for (int k = 0; k < KK; k++) g_idx[(b*NN + n)*KK + k] = b*NN + bi[k];
}

// ---------------- K3: gather + leaky + (h @ W2) + max_k + BN stats ----------------
// 256 threads: j = t&127 (output channel), cq = t>>7 (c-half owner).
// Each thread holds W2[c-half, j] in 64 regs; 32 points per block.
// cq=1 writes partial acc to smem; cq=0 reduces, max-pools, stores.
#define HP 136   // padded row stride (words), multiple of 4 for float4 alignment
__global__ void __launch_bounds__(256) k_edge(
    const float* __restrict__ W2, const float* __restrict__ b2)
{
    __shared__ __align__(16) float h1s[KK*HP];
    __shared__ __align__(16) float part[KK*HP];
    int t = threadIdx.x;
    int j  = t & 127;
    int cq = t >> 7;            // 0 or 1
    int c0 = cq * 64;
    int base = blockIdx.x * 32;

    float wcol[64];
    #pragma unroll
    for (int ci = 0; ci < 64; ci++) wcol[ci] = W2[(c0 + ci)*CC + j];
    float b2j = b2[j];

    float sumL = 0.f, sqL = 0.f;
    for (int p = 0; p < 32; p++) {
        int pt = base + p;
        float base_h = g_u[pt*CC + j] - g_v[pt*CC + j];
        // h rows split over the two c-groups (k = cq, cq+2, ...)
        for (int kk = cq; kk < KK; kk += 2) {
            int nb = g_idx[pt*KK + kk];           // uniform -> broadcast (global idx)
            float h = base_h + g_v[nb*CC + j];    // coalesced gather
            h1s[kk*HP + j] = (h >= 0.f) ? h : 0.2f*h;
        }
        __syncthreads();

        float acc[KK];
        #pragma unroll
        for (int k = 0; k < KK; k++) acc[k] = 0.f;
        #pragma unroll
        for (int ci = 0; ci < 64; ci += 4) {
            #pragma unroll
            for (int k = 0; k < KK; k++) {
                float4 h4 = *(const float4*)&h1s[k*HP + c0 + ci];  // broadcast
                float a = acc[k];
                a = fmaf(h4.x, wcol[ci  ], a);
                a = fmaf(h4.y, wcol[ci+1], a);
                a = fmaf(h4.z, wcol[ci+2], a);
                a = fmaf(h4.w, wcol[ci+3], a);
                acc[k] = a;
            }
        }
        if (cq) {
            #pragma unroll
            for (int k = 0; k < KK; k++) part[k*HP + j] = acc[k];
        }
        __syncthreads();
        if (!cq) {
            float m = acc[0] + part[0*HP + j];
            #pragma unroll
            for (int k = 1; k < KK; k++) m = fmaxf(m, acc[k] + part[k*HP + j]);
            float pre = m + b2j;
            g_pre[pt*CC + j] = pre;
            sumL += pre; sqL += pre*pre;
        }
    }
    if (!cq) {
        atomicAdd(&g_dsum[j], (double)sumL);
        atomicAdd(&g_dsqs[j], (double)sqL);
    }
}

// ---------------- K4: BN scale/shift ----------------
__global__ void k_bn(const float* __restrict__ gamma, const float* __restrict__ beta)
{
    int j = threadIdx.x;
    const double inv = 1.0 / (double)(BB*NN);
    double mean = g_dsum[j] * inv;
    double var  = g_dsqs[j] * inv - mean*mean;
    float sc = gamma[j] * rsqrtf((float)var + 1e-5f);
    g_scale[j] = sc;
    g_shift[j] = beta[j] - (float)mean * sc;
}

// ---------------- K5: transpose + BN apply + residual + ReLU ----------------
__global__ void __launch_bounds__(256) k_apply(
    const float* __restrict__ x, float* __restrict__ out)
{
    __shared__ float tile[32][33];
    int b  = blockIdx.z;
    int c0 = blockIdx.y * 32;
    int n0 = blockIdx.x * 32;
    int t = threadIdx.x;
    int cj = t & 31, i0 = t >> 5;

    for (int i = i0; i < 32; i += 8)
        tile[i][cj] = g_pre[((b*NN) + n0 + i)*CC + c0 + cj];   // coalesced over c
    __syncthreads();

    int nj = t & 31;
    for (int ci = i0; ci < 32; ci += 8) {
        int c = c0 + ci;
        int o = (b*CC + c)*NN + n0 + nj;
        float v = tile[nj][ci] * g_scale[c] + g_shift[c] + x[o];
        out[o] = v > 0.f ? v : 0.f;   // coalesced over n
    }
}

// ---------------- launch ----------------
extern "C" void kernel_launch(void* const* d_in, const int* in_sizes, int n_in,
                              void* d_out, int out_size)
{
    const float* x     = (const float*)d_in[0];
    const float* W1    = (const float*)d_in[1];
    const float* b1    = (const float*)d_in[2];
    const float* W2    = (const float*)d_in[3];
    const float* b2    = (const float*)d_in[4];
    const float* gamma = (const float*)d_in[5];
    const float* beta  = (const float*)d_in[6];
    float* out = (float*)d_out;

    k_init <<<1, 128>>>();
    k_point<<<BB*NN/16, 128>>>(x, W1, b1);
    k_knn  <<<dim3(NN/128, BB), 128>>>(x);
    k_edge <<<BB*NN/32, 256>>>(W2, b2);
    k_bn   <<<1, 128>>>(gamma, beta);
    k_apply<<<dim3(NN/32, CC/32, BB), 256>>>(x, out);
}

// round 8
// speedup vs baseline: 1.5311x; 1.5311x over previous
#include <cuda_runtime.h>

#define BB 16
#define CC 128
#define NN 1024
#define KK 9
#define NCH 4            // KNN m-chunks
#define MCH (NN/NCH)     // 256 m per chunk
#define NPT (BB*NN)      // 16384 points

// ---- scratch (device globals; no allocation allowed) ----
__device__ float  g_sq[NPT];
__device__ float  g_u[NPT*CC];       // u = f@W1[:C] + b1
__device__ float  g_v[NPT*CC];       // v = f@W1[C:]
__device__ int    g_idx[NPT*KK];     // GLOBAL point indices (b*NN + m)
__device__ float  g_pre[NPT*CC];     // pre-BN output, (b,n,c)
__device__ float  g_cd[NCH*KK*NPT];  // per-chunk candidate dists  [slot][pt]
__device__ int    g_ci[NCH*KK*NPT];  // per-chunk candidate global idx
__device__ double g_dsum[CC];
__device__ double g_dsqs[CC];
__device__ float  g_scale[CC];
__device__ float  g_shift[CC];

// ---------------- K0: zero BN accumulators ----------------
__global__ void k_init() {
    int t = threadIdx.x;
    g_dsum[t] = 0.0;
    g_dsqs[t] = 0.0;
}

// ---------------- K1: per-point sq, u, v ----------------
__global__ void __launch_bounds__(128) k_point(
    const float* __restrict__ x, const float* __restrict__ W1,
    const float* __restrict__ b1)
{
    __shared__ float fs[16*130];
    int t = threadIdx.x;
    int base = blockIdx.x * 16;
    int b = base / NN, n0 = base % NN;

    {
        int p = t & 15, c0 = t >> 4;
        #pragma unroll
        for (int i = 0; i < 16; i++) {
            int c = c0 + i*8;
            fs[p*130 + c] = x[(b*CC + c)*NN + n0 + p];
        }
    }
    __syncthreads();

    if (t < 16) {
        float s = 0.f;
        #pragma unroll 4
        for (int c = 0; c < CC; c++) { float f = fs[t*130+c]; s += f*f; }
        g_sq[base + t] = s;
    }

    int j = t;
    float accU[16], accV[16];
    #pragma unroll
    for (int p = 0; p < 16; p++) { accU[p]=0.f; accV[p]=0.f; }
    for (int c = 0; c < CC; c++) {
        float wa = W1[c*CC + j];
        float wb = W1[(CC+c)*CC + j];
        #pragma unroll
        for (int p = 0; p < 16; p++) {
            float f = fs[p*130 + c];
            accU[p] = fmaf(f, wa, accU[p]);
            accV[p] = fmaf(f, wb, accV[p]);
        }
    }
    float bj = b1[j];
    #pragma unroll
    for (int p = 0; p < 16; p++) {
        g_u[(base+p)*CC + j] = accU[p] + bj;
        g_v[(base+p)*CC + j] = accV[p];
    }
}

// ---------------- K2a: partial KNN over one m-chunk ----------------
// grid (NN/128, BB, NCH); thread owns one query row in registers.
__global__ void __launch_bounds__(128, 3) k_knn(const float* __restrict__ x)
{
    __shared__ float Am[CC*64];   // [c][m]
    __shared__ float sqs[64];
    int t  = threadIdx.x;
    int b  = blockIdx.y;
    int ch = blockIdx.z;
    int n  = blockIdx.x * 128 + t;

    float rf[CC];
    #pragma unroll
    for (int c = 0; c < CC; c++) rf[c] = x[(b*CC + c)*NN + n];
    float sq_n = g_sq[b*NN + n];

    float bd[KK]; int bi[KK];
    #pragma unroll
    for (int k = 0; k < KK; k++) { bd[k] = 3.4e38f; bi[k] = 0; }
    float wmax = 3.4e38f; int wpos = 0;

    for (int mt = 0; mt < MCH/64; mt++) {
        int mb = ch*MCH + mt*64;
        __syncthreads();
        for (int i = t; i < CC*64; i += 128) {
            int c = i >> 6, m = i & 63;
            Am[c*64 + m] = x[(b*CC + c)*NN + mb + m];
        }
        if (t < 64) sqs[t] = g_sq[b*NN + mb + t];
        __syncthreads();

        for (int mg = 0; mg < 64; mg += 4) {
            float d0=0.f, d1=0.f, d2a=0.f, d3=0.f;
            #pragma unroll
            for (int c = 0; c < CC; c++) {
                float4 am = *(const float4*)&Am[c*64 + mg];   // broadcast
                d0 = fmaf(rf[c], am.x, d0);
                d1 = fmaf(rf[c], am.y, d1);
                d2a= fmaf(rf[c], am.z, d2a);
                d3 = fmaf(rf[c], am.w, d3);
            }
            float dots[4] = {d0, d1, d2a, d3};
            #pragma unroll
            for (int q = 0; q < 4; q++) {
                int m = mb + mg + q;
                float d2v = sq_n + sqs[mg+q] - 2.f*dots[q];
                if (d2v < wmax) {
                    #pragma unroll
                    for (int k = 0; k < KK; k++)
                        if (k == wpos) { bd[k] = d2v; bi[k] = m; }
                    wmax = bd[0]; wpos = 0;
                    #pragma unroll
                    for (int k = 1; k < KK; k++)
                        if (bd[k] > wmax) { wmax = bd[k]; wpos = k; }
                }
            }
        }
    }
    int pt = b*NN + n;
    #pragma unroll
    for (int k = 0; k < KK; k++) {
        int slot = ch*KK + k;
        g_cd[slot*NPT + pt] = bd[k];
        g_ci[slot*NPT + pt] = b*NN + bi[k];   // global idx
    }
}

// ---------------- K2b: merge 4 chunk top-9 lists -> final top-9 ----------------
// (d, idx)-lexicographic smallest-9 == JAX top_k lower-index tie-break set.
// Order of the 9 is irrelevant downstream (max-pool is permutation-invariant).
__global__ void __launch_bounds__(256) k_merge()
{
    int pt = blockIdx.x * 256 + threadIdx.x;
    float bd[KK]; int bi[KK];
    #pragma unroll
    for (int k = 0; k < KK; k++) { bd[k] = 3.4e38f; bi[k] = 0x7fffffff; }
    float wmax = 3.4e38f; int wi = 0x7fffffff; int wpos = 0;

    for (int s = 0; s < NCH*KK; s++) {
        float d = g_cd[s*NPT + pt];
        int   i = g_ci[s*NPT + pt];
        if (d < wmax || (d == wmax && i < wi)) {
            #pragma unroll
            for (int k = 0; k < KK; k++)
                if (k == wpos) { bd[k] = d; bi[k] = i; }
            wmax = bd[0]; wi = bi[0]; wpos = 0;
            #pragma unroll
            for (int k = 1; k < KK; k++)
                if (bd[k] > wmax || (bd[k] == wmax && bi[k] > wi)) {
                    wmax = bd[k]; wi = bi[k]; wpos = k;
                }
        }
    }
    #pragma unroll
    for (int k = 0; k < KK; k++) g_idx[pt*KK + k] = bi[k];
}

// ---------------- K3: gather + leaky + (h @ W2) + max_k + BN stats ----------------
// Round-4 structure + double-buffered h1s + register prefetch of next point's
// gathers during the FMA loop; one barrier per point.
__global__ void __launch_bounds__(128, 3) k_edge(
    const float* __restrict__ W2, const float* __restrict__ b2)
{
    __shared__ __align__(16) float h1s[2][KK*CC];
    int j = threadIdx.x;
    int base = blockIdx.x * 16;

    float wcol[CC];
    #pragma unroll
    for (int c = 0; c < CC; c++) wcol[c] = W2[c*CC + j];   // coalesced across j
    float b2j = b2[j];

    float sumL = 0.f, sqL = 0.f;

    // prefetch point 0
    float ga[KK]; float base_h;
    {
        int pt = base;
        base_h = g_u[pt*CC + j] - g_v[pt*CC + j];
        #pragma unroll
        for (int k = 0; k < KK; k++) {
            int nb = g_idx[pt*KK + k];
            ga[k] = g_v[nb*CC + j];
        }
    }

    for (int p = 0; p < 16; p++) {
        int pt = base + p;
        float* hb = h1s[p & 1];
        #pragma unroll
        for (int k = 0; k < KK; k++) {
            float h = base_h + ga[k];
            hb[k*CC + j] = (h >= 0.f) ? h : 0.2f*h;
        }
        __syncthreads();   // one barrier per point (double buffer covers WAR)

        // prefetch next point's gathers — LDGs fly under the FMA loop below
        if (p < 15) {
            int pn = pt + 1;
            base_h = g_u[pn*CC + j] - g_v[pn*CC + j];
            #pragma unroll
            for (int k = 0; k < KK; k++) {
                int nb = g_idx[pn*KK + k];
                ga[k] = g_v[nb*CC + j];
            }
        }

        float acc[KK];
        #pragma unroll
        for (int k = 0; k < KK; k++) acc[k] = 0.f;
        #pragma unroll
        for (int c = 0; c < CC; c += 4) {
            #pragma unroll
            for (int k = 0; k < KK; k++) {
                float4 h4 = *(const float4*)&hb[k*CC + c];  // broadcast
                float a = acc[k];
                a = fmaf(h4.x, wcol[c  ], a);
                a = fmaf(h4.y, wcol[c+1], a);
                a = fmaf(h4.z, wcol[c+2], a);
                a = fmaf(h4.w, wcol[c+3], a);
                acc[k] = a;
            }
        }
        float m = acc[0];
        #pragma unroll
        for (int k = 1; k < KK; k++) m = fmaxf(m, acc[k]);
        float pre = m + b2j;
        g_pre[pt*CC + j] = pre;
        sumL += pre; sqL += pre*pre;
    }
    atomicAdd(&g_dsum[j], (double)sumL);
    atomicAdd(&g_dsqs[j], (double)sqL);
}

// ---------------- K4: BN scale/shift ----------------
__global__ void k_bn(const float* __restrict__ gamma, const float* __restrict__ beta)
{
    int j = threadIdx.x;
    const double inv = 1.0 / (double)(BB*NN);
    double mean = g_dsum[j] * inv;
    double var  = g_dsqs[j] * inv - mean*mean;
    float sc = gamma[j] * rsqrtf((float)var + 1e-5f);
    g_scale[j] = sc;
    g_shift[j] = beta[j] - (float)mean * sc;
}

// ---------------- K5: transpose + BN apply + residual + ReLU ----------------
__global__ void __launch_bounds__(256) k_apply(
    const float* __restrict__ x, float* __restrict__ out)
{
    __shared__ float tile[32][33];
    int b  = blockIdx.z;
    int c0 = blockIdx.y * 32;
    int n0 = blockIdx.x * 32;
    int t = threadIdx.x;
    int cj = t & 31, i0 = t >> 5;

    for (int i = i0; i < 32; i += 8)
        tile[i][cj] = g_pre[((b*NN) + n0 + i)*CC + c0 + cj];
    __syncthreads();

    int nj = t & 31;
    for (int ci = i0; ci < 32; ci += 8) {
        int c = c0 + ci;
        int o = (b*CC + c)*NN + n0 + nj;
        float v = tile[nj][ci] * g_scale[c] + g_shift[c] + x[o];
        out[o] = v > 0.f ? v : 0.f;
    }
}

// ---------------- launch ----------------
extern "C" void kernel_launch(void* const* d_in, const int* in_sizes, int n_in,
                              void* d_out, int out_size)
{
    const float* x     = (const float*)d_in[0];
    const float* W1    = (const float*)d_in[1];
    const float* b1    = (const float*)d_in[2];
    const float* W2    = (const float*)d_in[3];
    const float* b2    = (const float*)d_in[4];
    const float* gamma = (const float*)d_in[5];
    const float* beta  = (const float*)d_in[6];
    float* out = (float*)d_out;

    k_init <<<1, 128>>>();
    k_point<<<NPT/16, 128>>>(x, W1, b1);
    k_knn  <<<dim3(NN/128, BB, NCH), 128>>>(x);
    k_merge<<<NPT/256, 256>>>();
    k_edge <<<NPT/16, 128>>>(W2, b2);
    k_bn   <<<1, 128>>>(gamma, beta);
    k_apply<<<dim3(NN/32, CC/32, BB), 256>>>(x, out);
}

// round 10
// speedup vs baseline: 1.8942x; 1.2371x over previous
#include <cuda_runtime.h>
#include <cuda_bf16.h>
#include <cstdint>

#define BB 16
#define CC 128
#define NN 1024
#define KK 9
#define NCH 4            // topk m-chunks
#define MCH (NN/NCH)     // 256 m per chunk
#define NPT (BB*NN)      // 16384 points
#define ROW_W 68         // smem row stride in 32-bit words (64 data + 4 pad)

// ---- scratch (device globals; no allocation allowed) ----
__device__ float  g_sq[NPT];
__device__ float  g_u[NPT*CC];
__device__ float  g_v[NPT*CC];
__device__ int    g_idx[NPT*KK];
__device__ float  g_pre[NPT*CC];
__device__ float  g_dot[(size_t)NPT*NN];   // 67MB: dot[b][n][m] (symmetric)
__device__ float  g_cd[NCH*KK*NPT];
__device__ int    g_ci[NCH*KK*NPT];
__device__ double g_dsum[CC];
__device__ double g_dsqs[CC];
__device__ float  g_scale[CC];
__device__ float  g_shift[CC];

// warp-level bf16 MMA (PTX ISA 7.0+, compiles on compute_103 -> HMMA)
__device__ __forceinline__ void mma16816(float* c, const uint32_t* a, const uint32_t* b) {
    asm volatile(
        "mma.sync.aligned.m16n8k16.row.col.f32.bf16.bf16.f32 "
        "{%0,%1,%2,%3}, {%4,%5,%6,%7}, {%8,%9}, {%0,%1,%2,%3};"
        : "+f"(c[0]), "+f"(c[1]), "+f"(c[2]), "+f"(c[3])
        : "r"(a[0]), "r"(a[1]), "r"(a[2]), "r"(a[3]), "r"(b[0]), "r"(b[1]));
}

// ---------------- K0 ----------------
__global__ void k_init() {
    int t = threadIdx.x;
    g_dsum[t] = 0.0; g_dsqs[t] = 0.0;
}

// ---------------- K1: per-point sq, u, v (unchanged) ----------------
__global__ void __launch_bounds__(128) k_point(
    const float* __restrict__ x, const float* __restrict__ W1,
    const float* __restrict__ b1)
{
    __shared__ float fs[16*130];
    int t = threadIdx.x;
    int base = blockIdx.x * 16;
    int b = base / NN, n0 = base % NN;
    {
        int p = t & 15, c0 = t >> 4;
        #pragma unroll
        for (int i = 0; i < 16; i++) {
            int c = c0 + i*8;
            fs[p*130 + c] = x[(b*CC + c)*NN + n0 + p];
        }
    }
    __syncthreads();
    if (t < 16) {
        float s = 0.f;
        #pragma unroll 4
        for (int c = 0; c < CC; c++) { float f = fs[t*130+c]; s += f*f; }
        g_sq[base + t] = s;
    }
    int j = t;
    float accU[16], accV[16];
    #pragma unroll
    for (int p = 0; p < 16; p++) { accU[p]=0.f; accV[p]=0.f; }
    for (int c = 0; c < CC; c++) {
        float wa = W1[c*CC + j];
        float wb = W1[(CC+c)*CC + j];
        #pragma unroll
        for (int p = 0; p < 16; p++) {
            float f = fs[p*130 + c];
            accU[p] = fmaf(f, wa, accU[p]);
            accV[p] = fmaf(f, wb, accV[p]);
        }
    }
    float bj = b1[j];
    #pragma unroll
    for (int p = 0; p < 16; p++) {
        g_u[(base+p)*CC + j] = accU[p] + bj;
        g_v[(base+p)*CC + j] = accV[p];
    }
}

// ---------------- K2a: tensor-core gram via mma.sync (3-term double-bf16) ----------------
// CTA: dot tile (n0..+127) x (m0..+127), batch b. 256 thr = 8 warps, warp w owns
// 16 n-rows. Fragments gathered from padded smem (conflict-free: bank == lane).
__global__ void __launch_bounds__(256) k_gram(const float* __restrict__ x)
{
    extern __shared__ __align__(16) uint32_t sm[];
    uint32_t* SA_HI = sm;
    uint32_t* SA_LO = sm + 128*ROW_W;
    uint32_t* SB_HI = sm + 2*128*ROW_W;
    uint32_t* SB_LO = sm + 3*128*ROW_W;

    int tid = threadIdx.x;
    int b  = blockIdx.z;
    int n0 = blockIdx.x * 128, m0 = blockIdx.y * 128;

    // stage + split: grp 0 loads A rows (n), grp 1 loads B rows (m); coalesced over n/m
    {
        int grp = tid >> 7;
        int t   = tid & 127;
        int off = grp ? m0 : n0;
        uint32_t* HI = grp ? SB_HI : SA_HI;
        uint32_t* LO = grp ? SB_LO : SA_LO;
        const float* xb = x + (size_t)b*CC*NN + off + t;
        #pragma unroll 8
        for (int c = 0; c < CC; c += 2) {
            float v0 = xb[(size_t)c*NN];
            float v1 = xb[(size_t)(c+1)*NN];
            __nv_bfloat16 h0 = __float2bfloat16_rn(v0);
            __nv_bfloat16 h1 = __float2bfloat16_rn(v1);
            float l0 = v0 - __bfloat162float(h0);
            float l1 = v1 - __bfloat162float(h1);
            __nv_bfloat162 hp; hp.x = h0; hp.y = h1;
            __nv_bfloat162 lp = __floats2bfloat162_rn(l0, l1);
            HI[t*ROW_W + (c>>1)] = *(uint32_t*)&hp;
            LO[t*ROW_W + (c>>1)] = *(uint32_t*)&lp;
        }
    }
    __syncthreads();

    int w = tid >> 5, lane = tid & 31;
    int g = lane >> 2, tq = lane & 3;
    int ar = w*16 + g;

    float acc[16][4];
    #pragma unroll
    for (int i = 0; i < 16; i++) { acc[i][0]=acc[i][1]=acc[i][2]=acc[i][3]=0.f; }

    #pragma unroll
    for (int kt = 0; kt < 8; kt++) {
        int kw = kt*8 + tq;
        uint32_t ah[4], al[4];
        ah[0] = SA_HI[ ar     *ROW_W + kw  ];
        ah[1] = SA_HI[(ar+8)  *ROW_W + kw  ];
        ah[2] = SA_HI[ ar     *ROW_W + kw+4];
        ah[3] = SA_HI[(ar+8)  *ROW_W + kw+4];
        al[0] = SA_LO[ ar     *ROW_W + kw  ];
        al[1] = SA_LO[(ar+8)  *ROW_W + kw  ];
        al[2] = SA_LO[ ar     *ROW_W + kw+4];
        al[3] = SA_LO[(ar+8)  *ROW_W + kw+4];
        #pragma unroll
        for (int bt = 0; bt < 16; bt++) {
            int br = bt*8 + g;
            uint32_t bh[2], bl[2];
            bh[0] = SB_HI[br*ROW_W + kw  ];
            bh[1] = SB_HI[br*ROW_W + kw+4];
            bl[0] = SB_LO[br*ROW_W + kw  ];
            bl[1] = SB_LO[br*ROW_W + kw+4];
            mma16816(acc[bt], ah, bh);   // hi*hi
            mma16816(acc[bt], ah, bl);   // hi*lo
            mma16816(acc[bt], al, bh);   // lo*hi
        }
    }

    // writeback: c0:(g,2t) c1:(g,2t+1) c2:(g+8,2t) c3:(g+8,2t+1)
    int arow = n0 + w*16 + g;
    #pragma unroll
    for (int bt = 0; bt < 16; bt++) {
        int m = m0 + bt*8 + tq*2;
        float2 v01 = make_float2(acc[bt][0], acc[bt][1]);
        float2 v23 = make_float2(acc[bt][2], acc[bt][3]);
        *(float2*)&g_dot[(size_t)(b*NN + arow    )*NN + m] = v01;
        *(float2*)&g_dot[(size_t)(b*NN + arow + 8)*NN + m] = v23;
    }
}

// ---------------- K2b: chunked top-9 from dot matrix ----------------
// Reads dot[b][m][n] (== dot[b][n][m], symmetric) coalesced over n.
__global__ void __launch_bounds__(256) k_topk()
{
    int n  = blockIdx.x * 256 + threadIdx.x;
    int b  = blockIdx.y;
    int ch = blockIdx.z;
    int pt = b*NN + n;
    float sq_n = g_sq[pt];

    float bd[KK]; int bi[KK];
    #pragma unroll
    for (int k = 0; k < KK; k++) { bd[k] = 3.4e38f; bi[k] = 0; }
    float wmax = 3.4e38f; int wpos = 0;

    int mbase = ch*MCH;
    const float* drow = g_dot + (size_t)(b*NN + mbase)*NN + n;
    #pragma unroll 4
    for (int i = 0; i < MCH; i++) {
        int m = mbase + i;
        float dot = drow[(size_t)i*NN];
        float d2v = sq_n + g_sq[b*NN + m] - 2.f*dot;
        if (d2v < wmax) {
            #pragma unroll
            for (int k = 0; k < KK; k++)
                if (k == wpos) { bd[k] = d2v; bi[k] = m; }
            wmax = bd[0]; wpos = 0;
            #pragma unroll
            for (int k = 1; k < KK; k++)
                if (bd[k] > wmax) { wmax = bd[k]; wpos = k; }
        }
    }
    #pragma unroll
    for (int k = 0; k < KK; k++) {
        int slot = ch*KK + k;
        g_cd[slot*NPT + pt] = bd[k];
        g_ci[slot*NPT + pt] = b*NN + bi[k];
    }
}

// ---------------- K2c: merge 4 chunk top-9 lists -> final top-9 ----------------
__global__ void __launch_bounds__(128) k_merge()
{
    int pt = blockIdx.x * 128 + threadIdx.x;
    float bd[KK]; int bi[KK];
    #pragma unroll
    for (int k = 0; k < KK; k++) { bd[k] = 3.4e38f; bi[k] = 0x7fffffff; }
    float wmax = 3.4e38f; int wi = 0x7fffffff; int wpos = 0;

    for (int s = 0; s < NCH*KK; s++) {
        float d = g_cd[s*NPT + pt];
        int   i = g_ci[s*NPT + pt];
        if (d < wmax || (d == wmax && i < wi)) {
            #pragma unroll
            for (int k = 0; k < KK; k++)
                if (k == wpos) { bd[k] = d; bi[k] = i; }
            wmax = bd[0]; wi = bi[0]; wpos = 0;
            #pragma unroll
            for (int k = 1; k < KK; k++)
                if (bd[k] > wmax || (bd[k] == wmax && bi[k] > wi)) {
                    wmax = bd[k]; wi = bi[k]; wpos = k;
                }
        }
    }
    #pragma unroll
    for (int k = 0; k < KK; k++) g_idx[pt*KK + k] = bi[k];
}

// ---------------- K3: gather + leaky + (h @ W2) + max_k + BN stats (unchanged) ----------------
__global__ void __launch_bounds__(128, 3) k_edge(
    const float* __restrict__ W2, const float* __restrict__ b2)
{
    __shared__ __align__(16) float h1s[2][KK*CC];
    int j = threadIdx.x;
    int base = blockIdx.x * 16;

    float wcol[CC];
    #pragma unroll
    for (int c = 0; c < CC; c++) wcol[c] = W2[c*CC + j];
    float b2j = b2[j];

    float sumL = 0.f, sqL = 0.f;
    float ga[KK]; float base_h;
    {
        int pt = base;
        base_h = g_u[pt*CC + j] - g_v[pt*CC + j];
        #pragma unroll
        for (int k = 0; k < KK; k++) {
            int nb = g_idx[pt*KK + k];
            ga[k] = g_v[nb*CC + j];
        }
    }

    for (int p = 0; p < 16; p++) {
        int pt = base + p;
        float* hb = h1s[p & 1];
        #pragma unroll
        for (int k = 0; k < KK; k++) {
            float h = base_h + ga[k];
            hb[k*CC + j] = (h >= 0.f) ? h : 0.2f*h;
        }
        __syncthreads();

        if (p < 15) {
            int pn = pt + 1;
            base_h = g_u[pn*CC + j] - g_v[pn*CC + j];
            #pragma unroll
            for (int k = 0; k < KK; k++) {
                int nb = g_idx[pn*KK + k];
                ga[k] = g_v[nb*CC + j];
            }
        }

        float acc[KK];
        #pragma unroll
        for (int k = 0; k < KK; k++) acc[k] = 0.f;
        #pragma unroll
        for (int c = 0; c < CC; c += 4) {
            #pragma unroll
            for (int k = 0; k < KK; k++) {
                float4 h4 = *(const float4*)&hb[k*CC + c];
                float a = acc[k];
                a = fmaf(h4.x, wcol[c  ], a);
                a = fmaf(h4.y, wcol[c+1], a);
                a = fmaf(h4.z, wcol[c+2], a);
                a = fmaf(h4.w, wcol[c+3], a);
                acc[k] = a;
            }
        }
        float m = acc[0];
        #pragma unroll
        for (int k = 1; k < KK; k++) m = fmaxf(m, acc[k]);
        float pre = m + b2j;
        g_pre[pt*CC + j] = pre;
        sumL += pre; sqL += pre*pre;
    }
    atomicAdd(&g_dsum[j], (double)sumL);
    atomicAdd(&g_dsqs[j], (double)sqL);
}

// ---------------- K4: BN scale/shift ----------------
__global__ void k_bn(const float* __restrict__ gamma, const float* __restrict__ beta)
{
    int j = threadIdx.x;
    const double inv = 1.0 / (double)(BB*NN);
    double mean = g_dsum[j] * inv;
    double var  = g_dsqs[j] * inv - mean*mean;
    float sc = gamma[j] * rsqrtf((float)var + 1e-5f);
    g_scale[j] = sc;
    g_shift[j] = beta[j] - (float)mean * sc;
}

// ---------------- K5: transpose + BN apply + residual + ReLU ----------------
__global__ void __launch_bounds__(256) k_apply(
    const float* __restrict__ x, float* __restrict__ out)
{
    __shared__ float tile[32][33];
    int b  = blockIdx.z;
    int c0 = blockIdx.y * 32;
    int n0 = blockIdx.x * 32;
    int t = threadIdx.x;
    int cj = t & 31, i0 = t >> 5;

    for (int i = i0; i < 32; i += 8)
        tile[i][cj] = g_pre[((b*NN) + n0 + i)*CC + c0 + cj];
    __syncthreads();

    int nj = t & 31;
    for (int ci = i0; ci < 32; ci += 8) {
        int c = c0 + ci;
        int o = (b*CC + c)*NN + n0 + nj;
        float v = tile[nj][ci] * g_scale[c] + g_shift[c] + x[o];
        out[o] = v > 0.f ? v : 0.f;
    }
}

// ---------------- launch ----------------
#define GSM_BYTES (4*128*ROW_W*4)   // 139264

extern "C" void kernel_launch(void* const* d_in, const int* in_sizes, int n_in,
                              void* d_out, int out_size)
{
    const float* x     = (const float*)d_in[0];
    const float* W1    = (const float*)d_in[1];
    const float* b1    = (const float*)d_in[2];
    const float* W2    = (const float*)d_in[3];
    const float* b2    = (const float*)d_in[4];
    const float* gamma = (const float*)d_in[5];
    const float* beta  = (const float*)d_in[6];
    float* out = (float*)d_out;

    cudaFuncSetAttribute(k_gram, cudaFuncAttributeMaxDynamicSharedMemorySize, GSM_BYTES);

    k_init <<<1, 128>>>();
    k_point<<<NPT/16, 128>>>(x, W1, b1);
    k_gram <<<dim3(8, 8, BB), 256, GSM_BYTES>>>(x);
    k_topk <<<dim3(NN/256, BB, NCH), 256>>>();
    k_merge<<<NPT/128, 128>>>();
    k_edge <<<NPT/16, 128>>>(W2, b2);
    k_bn   <<<1, 128>>>(gamma, beta);
    k_apply<<<dim3(NN/32, CC/32, BB), 256>>>(x, out);
}